// round 6
// baseline (speedup 1.0000x reference)
#include <cuda_runtime.h>
#include <cstdint>

// TriLinear: out[b,q,k] = (Q.w1)[b,q] + (K.w2)[b,k] + sum_d Q[b,q,d]*w3[d]*K[b,k,d]
// B=32, L=1024, D=768.
//
// Strategy: per-batch GEMM C = Q @ (w3 (*) K)^T on tf32 mma.sync tensor cores,
// fp32 accumulate. Inputs rounded with cvt.rna (round-to-nearest) to avoid the
// biased truncation error of raw-fp32-as-tf32. Rank-1 logit terms computed
// in-block from the streamed tiles (zero extra HBM traffic), added in epilogue.
// Mainloop is double-buffered in smem AND 2-tile-deep register staged so DRAM
// latency (~600cyc) is covered by ~2 compute phases (~900cyc).

#define L_DIM 1024
#define D_DIM 768
#define BT    128        // block tile M == N
#define BK    16         // k-step per smem tile
#define SK    20         // padded smem stride (words): (20r+c) mod 32 is a
                         // permutation over (r in 0..7, c in 0..3) -> fragment
                         // LDS is bank-conflict-free
#define NKT   (D_DIM / BK)   // 48 k-tiles (even: clean 2x-unrolled loop)

__device__ __forceinline__ float to_tf32(float x) {
    float y;
    asm("cvt.rna.tf32.f32 %0, %1;" : "=f"(y) : "f"(x));
    return y;
}

__device__ __forceinline__ void mma_tf32(float* d, const uint32_t* a, const uint32_t* b) {
    asm volatile(
        "mma.sync.aligned.m16n8k8.row.col.f32.tf32.tf32.f32 "
        "{%0,%1,%2,%3}, {%4,%5,%6,%7}, {%8,%9}, {%0,%1,%2,%3};\n"
        : "+f"(d[0]), "+f"(d[1]), "+f"(d[2]), "+f"(d[3])
        : "r"(a[0]), "r"(a[1]), "r"(a[2]), "r"(a[3]),
          "r"(b[0]), "r"(b[1]));
}

struct Stage {
    float4 ra0, ra1, rb0, rb1, wv1, wv2, wv3;
};

__global__ __launch_bounds__(256, 1)
void trilinear_kernel(const float* __restrict__ Q,
                      const float* __restrict__ K,
                      const float* __restrict__ w1,
                      const float* __restrict__ w2,
                      const float* __restrict__ w3,
                      float* __restrict__ out)
{
    __shared__ float As[2][BT][SK];   // Q tile,      m-major, rounded tf32
    __shared__ float Bs[2][BT][SK];   // (w3*K) tile, n-major, rounded tf32
    __shared__ float qlog_s[BT];
    __shared__ float klog_s[BT];

    const int t  = threadIdx.x;
    const int bn = blockIdx.x;   // k-column tile
    const int bm = blockIdx.y;   // q-row tile
    const int bb = blockIdx.z;   // batch

    const float* Qb = Q + ((size_t)bb * L_DIM + (size_t)bm * BT) * D_DIM;
    const float* Kb = K + ((size_t)bb * L_DIM + (size_t)bn * BT) * D_DIM;

    // global->smem mapping: thread t handles rows (t>>2) and (t>>2)+64,
    // float4 at k-quad (t&3); 4 consecutive threads cover one 16-wide k row
    // -> per-row logit partials reduce via 2 shfls.
    const int m_lo = t >> 2;          // 0..63
    const int kq   = t & 3;           // which float4 of the 16-k row

    // warp / fragment geometry (8 warps = 2 m-rows x 4 n-cols of 64x32 tiles)
    const int lane = t & 31;
    const int w    = t >> 5;
    const int wm   = w >> 2;          // 0..1
    const int wn   = w & 3;           // 0..3
    const int gr   = lane >> 2;       // 0..7
    const int gc   = lane & 3;        // 0..3

    float acc[4][4][4];
    #pragma unroll
    for (int i = 0; i < 4; i++)
        #pragma unroll
        for (int j = 0; j < 4; j++)
            #pragma unroll
            for (int k2 = 0; k2 < 4; k2++)
                acc[i][j][k2] = 0.f;

    float qp0 = 0.f, qp1 = 0.f, kp0 = 0.f, kp1 = 0.f;   // logit partials

    auto load_tile = [&](int kt, Stage& s) {
        const int d = kt * BK + kq * 4;
        s.ra0 = *reinterpret_cast<const float4*>(Qb + (size_t)m_lo        * D_DIM + d);
        s.ra1 = *reinterpret_cast<const float4*>(Qb + (size_t)(m_lo + 64) * D_DIM + d);
        s.rb0 = *reinterpret_cast<const float4*>(Kb + (size_t)m_lo        * D_DIM + d);
        s.rb1 = *reinterpret_cast<const float4*>(Kb + (size_t)(m_lo + 64) * D_DIM + d);
        s.wv1 = *reinterpret_cast<const float4*>(w1 + d);   // 9 KB total: L1-resident
        s.wv2 = *reinterpret_cast<const float4*>(w2 + d);
        s.wv3 = *reinterpret_cast<const float4*>(w3 + d);
    };

    auto store_tile = [&](const Stage& s, int buf) {
        // logit partials in full fp32 (before tf32 rounding)
        qp0 += s.ra0.x*s.wv1.x + s.ra0.y*s.wv1.y + s.ra0.z*s.wv1.z + s.ra0.w*s.wv1.w;
        qp1 += s.ra1.x*s.wv1.x + s.ra1.y*s.wv1.y + s.ra1.z*s.wv1.z + s.ra1.w*s.wv1.w;
        kp0 += s.rb0.x*s.wv2.x + s.rb0.y*s.wv2.y + s.rb0.z*s.wv2.z + s.rb0.w*s.wv2.w;
        kp1 += s.rb1.x*s.wv2.x + s.rb1.y*s.wv2.y + s.rb1.z*s.wv2.z + s.rb1.w*s.wv2.w;

        const int kc = kq * 4;
        As[buf][m_lo     ][kc+0] = to_tf32(s.ra0.x);
        As[buf][m_lo     ][kc+1] = to_tf32(s.ra0.y);
        As[buf][m_lo     ][kc+2] = to_tf32(s.ra0.z);
        As[buf][m_lo     ][kc+3] = to_tf32(s.ra0.w);
        As[buf][m_lo + 64][kc+0] = to_tf32(s.ra1.x);
        As[buf][m_lo + 64][kc+1] = to_tf32(s.ra1.y);
        As[buf][m_lo + 64][kc+2] = to_tf32(s.ra1.z);
        As[buf][m_lo + 64][kc+3] = to_tf32(s.ra1.w);
        Bs[buf][m_lo     ][kc+0] = to_tf32(s.rb0.x * s.wv3.x);
        Bs[buf][m_lo     ][kc+1] = to_tf32(s.rb0.y * s.wv3.y);
        Bs[buf][m_lo     ][kc+2] = to_tf32(s.rb0.z * s.wv3.z);
        Bs[buf][m_lo     ][kc+3] = to_tf32(s.rb0.w * s.wv3.w);
        Bs[buf][m_lo + 64][kc+0] = to_tf32(s.rb1.x * s.wv3.x);
        Bs[buf][m_lo + 64][kc+1] = to_tf32(s.rb1.y * s.wv3.y);
        Bs[buf][m_lo + 64][kc+2] = to_tf32(s.rb1.z * s.wv3.z);
        Bs[buf][m_lo + 64][kc+3] = to_tf32(s.rb1.w * s.wv3.w);
    };

    auto compute = [&](int buf) {
        #pragma unroll
        for (int ks = 0; ks < 2; ks++) {
            const int kb = ks * 8;
            uint32_t afr[4][4], bfr[4][2];
            #pragma unroll
            for (int mf = 0; mf < 4; mf++) {
                const int mo = wm * 64 + mf * 16;
                afr[mf][0] = __float_as_uint(As[buf][mo + gr    ][kb + gc    ]);
                afr[mf][1] = __float_as_uint(As[buf][mo + gr + 8][kb + gc    ]);
                afr[mf][2] = __float_as_uint(As[buf][mo + gr    ][kb + gc + 4]);
                afr[mf][3] = __float_as_uint(As[buf][mo + gr + 8][kb + gc + 4]);
            }
            #pragma unroll
            for (int nf = 0; nf < 4; nf++) {
                const int no = wn * 32 + nf * 8;
                bfr[nf][0] = __float_as_uint(Bs[buf][no + gr][kb + gc    ]);
                bfr[nf][1] = __float_as_uint(Bs[buf][no + gr][kb + gc + 4]);
            }
            #pragma unroll
            for (int mf = 0; mf < 4; mf++)
                #pragma unroll
                for (int nf = 0; nf < 4; nf++)
                    mma_tf32(acc[mf][nf], afr[mf], bfr[nf]);
        }
    };

    // ---- mainloop: smem double-buffered, register staging 2 tiles deep ----
    // Schedule (kt even):
    //   half A: load(kt+2)->S0 ; compute(sm0) ; store S1(tile kt+1)->sm1 ; sync
    //   half B: load(kt+3)->S1 ; compute(sm1) ; store S0(tile kt+2)->sm0 ; sync
    // A load issued in one half is consumed at the END of the next half:
    // ~2 compute phases (~900cyc) of cover vs ~600cyc DRAM latency.
    Stage S0, S1;
    load_tile(0, S0);
    store_tile(S0, 0);
    load_tile(1, S1);
    __syncthreads();

    for (int kt = 0; kt < NKT; kt += 2) {
        // ---- half A: consume sm[0] (tile kt) ----
        if (kt + 2 < NKT) load_tile(kt + 2, S0);
        compute(0);
        store_tile(S1, 1);                        // tile kt+1 (kt+1 <= 47 always)
        __syncthreads();

        // ---- half B: consume sm[1] (tile kt+1) ----
        if (kt + 3 < NKT) load_tile(kt + 3, S1);
        compute(1);
        if (kt + 2 < NKT) store_tile(S0, 0);      // tile kt+2
        __syncthreads();
    }

    // ---- reduce logit partials (4 consecutive lanes per row) ----
    qp0 += __shfl_xor_sync(0xffffffffu, qp0, 1);
    qp0 += __shfl_xor_sync(0xffffffffu, qp0, 2);
    qp1 += __shfl_xor_sync(0xffffffffu, qp1, 1);
    qp1 += __shfl_xor_sync(0xffffffffu, qp1, 2);
    kp0 += __shfl_xor_sync(0xffffffffu, kp0, 1);
    kp0 += __shfl_xor_sync(0xffffffffu, kp0, 2);
    kp1 += __shfl_xor_sync(0xffffffffu, kp1, 1);
    kp1 += __shfl_xor_sync(0xffffffffu, kp1, 2);
    if ((t & 3) == 0) {
        qlog_s[m_lo]      = qp0;
        qlog_s[m_lo + 64] = qp1;
        klog_s[m_lo]      = kp0;
        klog_s[m_lo + 64] = kp1;
    }
    __syncthreads();

    // ---- epilogue: out = dot + qlog[q] + klog[k] ----
    // C-fragment layout (m16n8): c0,c1 -> row gr,   cols 2gc, 2gc+1
    //                            c2,c3 -> row gr+8, cols 2gc, 2gc+1
    float* Ob = out + ((size_t)bb * L_DIM + (size_t)bm * BT) * L_DIM + (size_t)bn * BT;
    #pragma unroll
    for (int mf = 0; mf < 4; mf++) {
        const int mo    = wm * 64 + mf * 16;
        const float ql0 = qlog_s[mo + gr];
        const float ql1 = qlog_s[mo + gr + 8];
        #pragma unroll
        for (int nf = 0; nf < 4; nf++) {
            const int no    = wn * 32 + nf * 8 + 2 * gc;
            const float kl0 = klog_s[no];
            const float kl1 = klog_s[no + 1];
            float2 v0, v1;
            v0.x = acc[mf][nf][0] + ql0 + kl0;
            v0.y = acc[mf][nf][1] + ql0 + kl1;
            v1.x = acc[mf][nf][2] + ql1 + kl0;
            v1.y = acc[mf][nf][3] + ql1 + kl1;
            *reinterpret_cast<float2*>(Ob + (size_t)(mo + gr    ) * L_DIM + no) = v0;
            *reinterpret_cast<float2*>(Ob + (size_t)(mo + gr + 8) * L_DIM + no) = v1;
        }
    }
}

extern "C" void kernel_launch(void* const* d_in, const int* in_sizes, int n_in,
                              void* d_out, int out_size)
{
    const float* Q  = (const float*)d_in[0];
    const float* K  = (const float*)d_in[1];
    const float* w1 = (const float*)d_in[2];
    const float* w2 = (const float*)d_in[3];
    const float* w3 = (const float*)d_in[4];

    const int batches = in_sizes[0] / (L_DIM * D_DIM);   // 32
    dim3 grid(L_DIM / BT, L_DIM / BT, batches);          // (8, 8, 32)
    trilinear_kernel<<<grid, 256>>>(Q, K, w1, w2, w3, (float*)d_out);
}

// round 10
// speedup vs baseline: 1.2485x; 1.2485x over previous
#include <cuda_runtime.h>
#include <cstdint>

// TriLinear: out[b,q,k] = (Q.w1)[b,q] + (K.w2)[b,k] + sum_d Q[b,q,d]*w3[d]*K[b,k,d]
// B=32, L=1024, D=768.
//
// tf32 mma.sync GEMM C = Q @ (w3 (*) K)^T, fp32 accumulate.
// - 128x256 block tile, 8 warps of 64x64 (2x fragment reuse vs 64x32)
// - cp.async 4-stage smem pipeline (raw fp32 in smem; no register staging)
// - transform at fragment-load time: cvt.rna tf32 (+ w3 multiply for B)
// - rank-1 logit terms accumulated from raw fragment values (exactly-once
//   coverage: wn==0 warps -> qlog, wm==0 warps -> klog), quad-shfl reduced,
//   added in the epilogue. Zero extra HBM traffic.

#define L_DIM 1024
#define D_DIM 768
#define BM    128
#define BN    256
#define BK    16
#define NKT   (D_DIM / BK)     // 48
#define SKA   20               // padded row stride (floats): (20r+c)%32 is a
                               // permutation over r0..7 x c0..3 -> conflict-free
#define THREADS 256
#define NSTAGE  4

// ---- dynamic smem layout (bytes) ----
#define SM_W      0                        // w1|w2|w3 : 3*768*4 = 9216
#define SM_QLOG   9216                     // 128 floats
#define SM_KLOG   9728                     // 256 floats
#define SM_TILES  10752                    // 16B-aligned
#define A_STAGE_B (BM * SKA * 4)           // 10240
#define B_STAGE_B (BN * SKA * 4)           // 20480
#define STAGE_B   (A_STAGE_B + B_STAGE_B)  // 30720
#define SM_TOTAL  (SM_TILES + NSTAGE * STAGE_B)   // 133632

__device__ __forceinline__ float to_tf32(float x) {
    float y;
    asm("cvt.rna.tf32.f32 %0, %1;" : "=f"(y) : "f"(x));
    return y;
}

__device__ __forceinline__ void mma_tf32(float* d, const uint32_t* a, const uint32_t* b) {
    asm volatile(
        "mma.sync.aligned.m16n8k8.row.col.f32.tf32.tf32.f32 "
        "{%0,%1,%2,%3}, {%4,%5,%6,%7}, {%8,%9}, {%0,%1,%2,%3};\n"
        : "+f"(d[0]), "+f"(d[1]), "+f"(d[2]), "+f"(d[3])
        : "r"(a[0]), "r"(a[1]), "r"(a[2]), "r"(a[3]),
          "r"(b[0]), "r"(b[1]));
}

__device__ __forceinline__ uint32_t smem_u32(const void* p) {
    uint32_t a;
    asm("{ .reg .u64 t; cvta.to.shared.u64 t, %1; cvt.u32.u64 %0, t; }"
        : "=r"(a) : "l"(p));
    return a;
}

__device__ __forceinline__ void cpa16(uint32_t dst, const float* src) {
    asm volatile("cp.async.cg.shared.global [%0], [%1], 16;"
                 :: "r"(dst), "l"(src) : "memory");
}

__device__ __forceinline__ void cpa_commit() {
    asm volatile("cp.async.commit_group;" ::: "memory");
}

__device__ __forceinline__ void cpa_wait2() {
    asm volatile("cp.async.wait_group 2;" ::: "memory");
}

__global__ __launch_bounds__(THREADS, 1)
void trilinear_kernel(const float* __restrict__ Q,
                      const float* __restrict__ K,
                      const float* __restrict__ w1,
                      const float* __restrict__ w2,
                      const float* __restrict__ w3,
                      float* __restrict__ out)
{
    extern __shared__ char smc[];
    const uint32_t sb = smem_u32(smc);

    const int t    = threadIdx.x;
    const int lane = t & 31;
    const int wid  = t >> 5;
    const int wm   = wid >> 2;        // 0..1  (64-row slice)
    const int wn   = wid & 3;         // 0..3  (64-col slice)
    const int gr   = lane >> 2;       // 0..7
    const int gc   = lane & 3;        // 0..3

    const int bn = blockIdx.x, bm = blockIdx.y, bb = blockIdx.z;
    const float* Qb = Q + ((size_t)bb * L_DIM + (size_t)bm * BM) * D_DIM;
    const float* Kb = K + ((size_t)bb * L_DIM + (size_t)bn * BN) * D_DIM;

    // producer mapping: 4 consecutive threads cover one 16-float k-row
    const int prow = t >> 2;          // 0..63
    const int pkq  = t & 3;           // float4 index within the 16-float row

    // ---- stage w1/w2/w3 into smem (ordinary loads; visible after 1st sync) ----
    {
        float* wsm = (float*)(smc + SM_W);
        for (int i = t; i < D_DIM; i += THREADS) {
            wsm[i]             = __ldg(w1 + i);
            wsm[i + D_DIM]     = __ldg(w2 + i);
            wsm[i + 2 * D_DIM] = __ldg(w3 + i);
        }
    }

    auto issue_stage = [&](int c) {
        const int s = c & (NSTAGE - 1);
        const int koff = c * BK + pkq * 4;
        const uint32_t abase = sb + SM_TILES + s * STAGE_B;
        const uint32_t bbase = abase + A_STAGE_B;
        // A: rows prow, prow+64
        cpa16(abase + (uint32_t)(prow        * SKA + pkq * 4) * 4,
              Qb + (size_t)prow        * D_DIM + koff);
        cpa16(abase + (uint32_t)((prow + 64) * SKA + pkq * 4) * 4,
              Qb + (size_t)(prow + 64) * D_DIM + koff);
        // B: rows prow + 64*i, i = 0..3
        #pragma unroll
        for (int i = 0; i < 4; i++) {
            const int r = prow + 64 * i;
            cpa16(bbase + (uint32_t)(r * SKA + pkq * 4) * 4,
                  Kb + (size_t)r * D_DIM + koff);
        }
    };

    float acc[4][8][4];
    #pragma unroll
    for (int i = 0; i < 4; i++)
        #pragma unroll
        for (int j = 0; j < 8; j++)
            #pragma unroll
            for (int k2 = 0; k2 < 4; k2++)
                acc[i][j][k2] = 0.f;

    float qp0[4], qp1[4], kp[8];      // logit partials (raw fp32)
    #pragma unroll
    for (int i = 0; i < 4; i++) { qp0[i] = 0.f; qp1[i] = 0.f; }
    #pragma unroll
    for (int i = 0; i < 8; i++) kp[i] = 0.f;

    // ---- prologue: fill 3 stages ----
    issue_stage(0); cpa_commit();
    issue_stage(1); cpa_commit();
    issue_stage(2); cpa_commit();

    const float* wsm = (const float*)(smc + SM_W);

    // Pipeline invariant: stage c is the (c+1)-th committed group; before the
    // wait in iter c there are 3+c commits, so wait_group 2 -> stage c done.
    for (int c = 0; c < NKT; c++) {
        cpa_wait2();
        __syncthreads();              // all threads' stage-c data visible; also
                                      // closes iter c-1 reads of buf (c-1)%4

        if (c + 3 < NKT) issue_stage(c + 3);
        cpa_commit();                 // commit every iter (empty groups are fine)

        const int s = c & (NSTAGE - 1);
        const float* Ab = (const float*)(smc + SM_TILES + s * STAGE_B);
        const float* Bb = (const float*)(smc + SM_TILES + s * STAGE_B + A_STAGE_B);

        #pragma unroll
        for (int ks = 0; ks < 2; ks++) {
            const int kb   = ks * 8;
            const int kg0  = c * BK + kb + gc;
            const float w1v0 = wsm[kg0],             w1v1 = wsm[kg0 + 4];
            const float w2v0 = wsm[D_DIM + kg0],     w2v1 = wsm[D_DIM + kg0 + 4];
            const float w3v0 = wsm[2 * D_DIM + kg0], w3v1 = wsm[2 * D_DIM + kg0 + 4];

            uint32_t afr[4][4], bfr[8][2];
            #pragma unroll
            for (int mf = 0; mf < 4; mf++) {
                const int mo = wm * 64 + mf * 16;
                const float a0 = Ab[(mo + gr    ) * SKA + kb + gc    ];
                const float a1 = Ab[(mo + gr + 8) * SKA + kb + gc    ];
                const float a2 = Ab[(mo + gr    ) * SKA + kb + gc + 4];
                const float a3 = Ab[(mo + gr + 8) * SKA + kb + gc + 4];
                if (wn == 0) {                      // exactly-once qlog coverage
                    qp0[mf] += a0 * w1v0 + a2 * w1v1;
                    qp1[mf] += a1 * w1v0 + a3 * w1v1;
                }
                afr[mf][0] = __float_as_uint(to_tf32(a0));
                afr[mf][1] = __float_as_uint(to_tf32(a1));
                afr[mf][2] = __float_as_uint(to_tf32(a2));
                afr[mf][3] = __float_as_uint(to_tf32(a3));
            }
            #pragma unroll
            for (int nf = 0; nf < 8; nf++) {
                const int no = wn * 64 + nf * 8;
                const float b0 = Bb[(no + gr) * SKA + kb + gc    ];
                const float b1 = Bb[(no + gr) * SKA + kb + gc + 4];
                if (wm == 0) {                      // exactly-once klog coverage
                    kp[nf] += b0 * w2v0 + b1 * w2v1;
                }
                bfr[nf][0] = __float_as_uint(to_tf32(b0 * w3v0));
                bfr[nf][1] = __float_as_uint(to_tf32(b1 * w3v1));
            }
            #pragma unroll
            for (int mf = 0; mf < 4; mf++)
                #pragma unroll
                for (int nf = 0; nf < 8; nf++)
                    mma_tf32(acc[mf][nf], afr[mf], bfr[nf]);
        }
    }

    // ---- reduce logit partials (quad shfl over lanes 4*gr + gc) ----
    float* qlog_s = (float*)(smc + SM_QLOG);
    float* klog_s = (float*)(smc + SM_KLOG);
    if (wn == 0) {
        #pragma unroll
        for (int mf = 0; mf < 4; mf++) {
            float v0 = qp0[mf], v1 = qp1[mf];
            v0 += __shfl_xor_sync(0xffffffffu, v0, 1);
            v0 += __shfl_xor_sync(0xffffffffu, v0, 2);
            v1 += __shfl_xor_sync(0xffffffffu, v1, 1);
            v1 += __shfl_xor_sync(0xffffffffu, v1, 2);
            if (gc == 0) {
                qlog_s[wm * 64 + mf * 16 + gr    ] = v0;
                qlog_s[wm * 64 + mf * 16 + gr + 8] = v1;
            }
        }
    }
    if (wm == 0) {
        #pragma unroll
        for (int nf = 0; nf < 8; nf++) {
            float v = kp[nf];
            v += __shfl_xor_sync(0xffffffffu, v, 1);
            v += __shfl_xor_sync(0xffffffffu, v, 2);
            if (gc == 0) klog_s[wn * 64 + nf * 8 + gr] = v;
        }
    }
    __syncthreads();

    // ---- epilogue: out = dot + qlog[q] + klog[k] ----
    float* Ob = out + ((size_t)bb * L_DIM + (size_t)bm * BM) * L_DIM + (size_t)bn * BN;
    #pragma unroll
    for (int mf = 0; mf < 4; mf++) {
        const int mo    = wm * 64 + mf * 16;
        const float ql0 = qlog_s[mo + gr];
        const float ql1 = qlog_s[mo + gr + 8];
        #pragma unroll
        for (int nf = 0; nf < 8; nf++) {
            const int no    = wn * 64 + nf * 8 + 2 * gc;
            const float kl0 = klog_s[no];
            const float kl1 = klog_s[no + 1];
            float2 v0, v1;
            v0.x = acc[mf][nf][0] + ql0 + kl0;
            v0.y = acc[mf][nf][1] + ql0 + kl1;
            v1.x = acc[mf][nf][2] + ql1 + kl0;
            v1.y = acc[mf][nf][3] + ql1 + kl1;
            *reinterpret_cast<float2*>(Ob + (size_t)(mo + gr    ) * L_DIM + no) = v0;
            *reinterpret_cast<float2*>(Ob + (size_t)(mo + gr + 8) * L_DIM + no) = v1;
        }
    }
}

extern "C" void kernel_launch(void* const* d_in, const int* in_sizes, int n_in,
                              void* d_out, int out_size)
{
    const float* Q  = (const float*)d_in[0];
    const float* K  = (const float*)d_in[1];
    const float* w1 = (const float*)d_in[2];
    const float* w2 = (const float*)d_in[3];
    const float* w3 = (const float*)d_in[4];

    // Unconditional (idempotent, deterministic, capture-safe) — no static guards.
    cudaFuncSetAttribute(trilinear_kernel,
                         cudaFuncAttributeMaxDynamicSharedMemorySize, SM_TOTAL);

    const int batches = in_sizes[0] / (L_DIM * D_DIM);   // 32
    dim3 grid(L_DIM / BN, L_DIM / BM, batches);          // (4, 8, 32)
    trilinear_kernel<<<grid, THREADS, SM_TOTAL>>>(Q, K, w1, w2, w3, (float*)d_out);
}